// round 2
// baseline (speedup 1.0000x reference)
#include <cuda_runtime.h>
#include <cstdint>

typedef unsigned long long ull;

#define BB   128   // batch
#define TT   512   // time
#define FF   128   // input features
#define UU   512   // GRU units
#define NCTA 128   // persistent grid (<= 148 SMs -> co-resident)
#define NTHR 256
#define KC   64    // K chunk rows

// ---------------- static device scratch ----------------
__device__ float g_xT[(size_t)TT * FF * BB];        // x transposed to (T, F, B)
__device__ float g_hseq[(size_t)TT * UU * BB];      // layer-1 outputs (T, U, B)
__device__ float g_h1[2 * UU * BB];                 // layer-1 h ping-pong
__device__ float g_h2[2 * UU * BB];                 // layer-2 h ping-pong
__device__ int   g_bar[2 * TT];                     // per-step barrier counters

// ---------------- helpers ----------------
__device__ __forceinline__ ull fma2(ull a, ull b, ull c) {
    ull d; asm("fma.rn.f32x2 %0, %1, %2, %3;" : "=l"(d) : "l"(a), "l"(b), "l"(c)); return d;
}
__device__ __forceinline__ ull add2(ull a, ull b) {
    ull d; asm("add.rn.f32x2 %0, %1, %2;" : "=l"(d) : "l"(a), "l"(b)); return d;
}
__device__ __forceinline__ float2 asf2(ull v) {
    float2 f; asm("mov.b64 {%0, %1}, %2;" : "=f"(f.x), "=f"(f.y) : "l"(v)); return f;
}
__device__ __forceinline__ float sigm(float v) { return 1.0f / (1.0f + __expf(-v)); }

// SMEM layout: per-CTA weight slices (duplicated pairs for f32x2) + act chunks
struct Smem {
    float w1[640 * 24];     // layer1: (640 k) x (4 units) x (3 gates x dup2)
    float w2[1024 * 24];    // layer2: (1024 k) x 4 x 6
    union {
        float act[2][KC * BB];      // double-buffered activation chunk
        float red[3 * 64 * 32];     // k-split partial reduction
    } u;
};
// sizeof(Smem) = (15360 + 24576 + 16384) * 4 = 225280 bytes

__device__ __forceinline__ void cp_chunk(float* dst, const float* src, int tid) {
    uint32_t d = (uint32_t)__cvta_generic_to_shared(dst);
    #pragma unroll
    for (int i = 0; i < 8; i++) {
        int f = tid + NTHR * i;      // float4 index, 2048 total (64 rows x 32)
        asm volatile("cp.async.cg.shared.global [%0], [%1], 16;"
                     :: "r"(d + f * 16), "l"(src + f * 4) : "memory");
    }
    asm volatile("cp.async.commit_group;" ::: "memory");
}
__device__ __forceinline__ void cp_wait_all() {
    asm volatile("cp.async.wait_group 0;" ::: "memory");
}

__device__ __forceinline__ void grid_barrier(int* bar) {
    __syncthreads();
    if (threadIdx.x == 0) {
        int old;
        asm volatile("atom.acq_rel.gpu.global.add.u32 %0, [%1], 1;"
                     : "=r"(old) : "l"(bar) : "memory");
        if (old != NCTA - 1) {
            int v;
            do {
                asm volatile("ld.acquire.gpu.global.u32 %0, [%1];"
                             : "=r"(v) : "l"(bar) : "memory");
            } while (v < NCTA);
        }
    }
    __syncthreads();
}

__device__ void load_weights(float* dst, const float* Wi, const float* Ur,
                             int inRows, int K, int cta, int tid)
{
    for (int idx = tid; idx < K * 12; idx += NTHR) {
        int k = idx / 12, c = idx - k * 12;
        int u = c / 3, g = c - u * 3;
        int col = g * UU + cta * 4 + u;
        float v = (k < inRows) ? Wi[(size_t)k * (3 * UU) + col]
                               : Ur[(size_t)(k - inRows) * (3 * UU) + col];
        dst[k * 24 + u * 6 + g * 2]     = v;   // duplicated pair for f32x2
        dst[k * 24 + u * 6 + g * 2 + 1] = v;
    }
}

// accumulate one KC-row chunk: 16 k-iters (k-split by 4), 12 FMA2 each
__device__ __forceinline__ void compute_chunk(
    const float* A, const float* w, int kg, int unit, int bg,
    ull* az, ull* ar, ull* ah)
{
    #pragma unroll
    for (int i = 0; i < KC / 4; i++) {
        int k = 4 * i + kg;
        const float* ap = A + k * BB + bg * 8;
        ulonglong2 p01 = *reinterpret_cast<const ulonglong2*>(ap);       // batches 0-3
        ulonglong2 p23 = *reinterpret_cast<const ulonglong2*>(ap + 4);   // batches 4-7
        const float* wp = w + k * 24 + unit * 6;
        ull wz = *reinterpret_cast<const ull*>(wp);
        ull wr = *reinterpret_cast<const ull*>(wp + 2);
        ull wh = *reinterpret_cast<const ull*>(wp + 4);
        az[0] = fma2(p01.x, wz, az[0]); az[1] = fma2(p01.y, wz, az[1]);
        az[2] = fma2(p23.x, wz, az[2]); az[3] = fma2(p23.y, wz, az[3]);
        ar[0] = fma2(p01.x, wr, ar[0]); ar[1] = fma2(p01.y, wr, ar[1]);
        ar[2] = fma2(p23.x, wr, ar[2]); ar[3] = fma2(p23.y, wr, ar[3]);
        ah[0] = fma2(p01.x, wh, ah[0]); ah[1] = fma2(p01.y, wh, ah[1]);
        ah[2] = fma2(p23.x, wh, ah[2]); ah[3] = fma2(p23.y, wh, ah[3]);
    }
}

template <int K, int INROWS, bool WRITE_SEQ>
__device__ __forceinline__ void layer_steps(
    Smem* sm, const float* wsm,
    const float* inBase, size_t inStride,
    const float* bi, const float* br,
    float* hbuf, float* hseqOut, int* bars,
    int kg, int unit, int bg, int j, int tid)
{
    const int NCH = K / KC, INCH = INROWS / KC;
    float bZ  = bi[j] + br[j];
    float bR  = bi[UU + j] + br[UU + j];
    float biH = bi[2 * UU + j];
    float brH = br[2 * UU + j];

    #pragma unroll 1
    for (int t = 0; t < TT; t++) {
        const float* src0  = inBase + (size_t)t * inStride;
        const float* rec   = hbuf + (size_t)(t & 1) * (UU * BB);
        float*       hnext = hbuf + (size_t)((t + 1) & 1) * (UU * BB);

        cp_chunk(sm->u.act[0], src0, tid);   // prologue: chunk 0

        ull az[4]  = {0, 0, 0, 0}, ar[4]  = {0, 0, 0, 0};
        ull ahx[4] = {0, 0, 0, 0}, ahr[4] = {0, 0, 0, 0};

        #pragma unroll 1
        for (int ch = 0; ch < NCH; ch++) {
            cp_wait_all();
            __syncthreads();                 // chunk ch ready; everyone done with ch-1
            if (ch + 1 < NCH) {
                int c = ch + 1;
                const float* s = (c < INCH) ? (src0 + (size_t)c * KC * BB)
                                            : (rec  + (size_t)(c - INCH) * KC * BB);
                cp_chunk(sm->u.act[c & 1], s, tid);
            }
            const float* A = sm->u.act[ch & 1];
            const float* w = wsm + ch * KC * 24;
            if (ch < INCH) compute_chunk(A, w, kg, unit, bg, az, ar, ahx);
            else           compute_chunk(A, w, kg, unit, bg, az, ar, ahr);
        }
        __syncthreads();

        // k-split reduction (partials into smem, kg==0 sums + finalizes)
        int slot = unit * 16 + bg;           // 0..63
        if (kg > 0) {
            float* r = &sm->u.red[((kg - 1) * 64 + slot) * 32];
            #pragma unroll
            for (int p = 0; p < 4; p++) {
                reinterpret_cast<ull*>(r)[p]      = az[p];
                reinterpret_cast<ull*>(r)[4 + p]  = ar[p];
                reinterpret_cast<ull*>(r)[8 + p]  = ahx[p];
                reinterpret_cast<ull*>(r)[12 + p] = ahr[p];
            }
        }
        __syncthreads();
        if (kg == 0) {
            #pragma unroll
            for (int s = 0; s < 3; s++) {
                const float* r = &sm->u.red[(s * 64 + slot) * 32];
                #pragma unroll
                for (int p = 0; p < 4; p++) {
                    az[p]  = add2(az[p],  reinterpret_cast<const ull*>(r)[p]);
                    ar[p]  = add2(ar[p],  reinterpret_cast<const ull*>(r)[4 + p]);
                    ahx[p] = add2(ahx[p], reinterpret_cast<const ull*>(r)[8 + p]);
                    ahr[p] = add2(ahr[p], reinterpret_cast<const ull*>(r)[12 + p]);
                }
            }
            const float* hp = rec + (size_t)j * BB + bg * 8;
            float4 h0  = __ldcg((const float4*)hp);
            float4 h1v = __ldcg((const float4*)(hp + 4));
            float hpv[8] = {h0.x, h0.y, h0.z, h0.w, h1v.x, h1v.y, h1v.z, h1v.w};
            float hn[8];
            #pragma unroll
            for (int p = 0; p < 4; p++) {
                float2 z2 = asf2(az[p]),  r2  = asf2(ar[p]);
                float2 x2 = asf2(ahx[p]), rr2 = asf2(ahr[p]);
                float z  = sigm(z2.x + bZ);
                float rg = sigm(r2.x + bR);
                float hh = fmaxf(x2.x + biH + rg * (rr2.x + brH), 0.0f);
                hn[2 * p]     = z * hpv[2 * p] + (1.0f - z) * hh;
                z  = sigm(z2.y + bZ);
                rg = sigm(r2.y + bR);
                hh = fmaxf(x2.y + biH + rg * (rr2.y + brH), 0.0f);
                hn[2 * p + 1] = z * hpv[2 * p + 1] + (1.0f - z) * hh;
            }
            float* hout = hnext + (size_t)j * BB + bg * 8;
            *reinterpret_cast<float4*>(hout)     = make_float4(hn[0], hn[1], hn[2], hn[3]);
            *reinterpret_cast<float4*>(hout + 4) = make_float4(hn[4], hn[5], hn[6], hn[7]);
            if (WRITE_SEQ) {
                float* so = hseqOut + (size_t)t * (UU * BB) + (size_t)j * BB + bg * 8;
                *reinterpret_cast<float4*>(so)     = make_float4(hn[0], hn[1], hn[2], hn[3]);
                *reinterpret_cast<float4*>(so + 4) = make_float4(hn[4], hn[5], hn[6], hn[7]);
            }
        }
        grid_barrier(&bars[t]);
    }
}

__global__ void __launch_bounds__(NTHR, 1) gru_persist(
    const float* __restrict__ xT,
    const float* __restrict__ W1, const float* __restrict__ U1,
    const float* __restrict__ bi1, const float* __restrict__ br1,
    const float* __restrict__ W2, const float* __restrict__ U2,
    const float* __restrict__ bi2, const float* __restrict__ br2,
    float* hseq, float* h1, float* h2, int* bars)
{
    extern __shared__ Smem smem_dyn[];
    Smem* sm = &smem_dyn[0];
    int tid = threadIdx.x;
    int cta = blockIdx.x;

    load_weights(sm->w1, W1, U1, 128, 640,  cta, tid);
    load_weights(sm->w2, W2, U2, 512, 1024, cta, tid);
    __syncthreads();

    int kg   = tid >> 6;          // k-split group 0..3
    int bghi = (tid >> 5) & 1;
    int unit = (tid >> 3) & 3;    // unit within CTA (weight broadcast lanes)
    int bglo = tid & 7;
    int bg   = bghi * 8 + bglo;   // batch group 0..15 (8 batches each)
    int j    = cta * 4 + unit;    // global unit index

    layer_steps<640, 128, true>(sm, sm->w1, xT, (size_t)FF * BB,
                                bi1, br1, h1, hseq, bars, kg, unit, bg, j, tid);
    layer_steps<1024, 512, false>(sm, sm->w2, hseq, (size_t)UU * BB,
                                  bi2, br2, h2, nullptr, bars + TT, kg, unit, bg, j, tid);
}

// ---------------------------------------------------------------------------
__global__ void init_kernel(float* h1, float* h2, int* bars)
{
    int i = blockIdx.x * blockDim.x + threadIdx.x;
    if (i < UU * BB) { h1[i] = 0.0f; h2[i] = 0.0f; }
    if (i < 2 * TT)  bars[i] = 0;
}

// x (B, T, F) -> xT (T, F, B)
__global__ void transpose_x(const float* __restrict__ x, float* __restrict__ xT)
{
    __shared__ float tile[32][33];
    const int t  = blockIdx.x;
    const int bb = blockIdx.y * 32;
    const int ib = blockIdx.z * 32;
    const int tx = threadIdx.x, ty = threadIdx.y;   // 32 x 8

    #pragma unroll
    for (int r = 0; r < 4; r++)
        tile[ty + 8 * r][tx] = x[(size_t)(bb + ty + 8 * r) * TT * FF + (size_t)t * FF + ib + tx];
    __syncthreads();
    #pragma unroll
    for (int r = 0; r < 4; r++)
        xT[(size_t)t * FF * BB + (size_t)(ib + ty + 8 * r) * BB + bb + tx] = tile[tx][ty + 8 * r];
}

__global__ void head_kernel(const float* __restrict__ h,   // (U, B) final h2
                            const float* __restrict__ Wd,  // (U, 1)
                            const float* __restrict__ bd,
                            float* __restrict__ out)
{
    int b = threadIdx.x;
    float acc = bd[0];
    #pragma unroll 8
    for (int k = 0; k < UU; k++)
        acc += h[k * BB + b] * __ldg(&Wd[k]);
    out[b] = acc;
}

// ---------------------------------------------------------------------------
extern "C" void kernel_launch(void* const* d_in, const int* in_sizes, int n_in,
                              void* d_out, int out_size)
{
    const float* x   = (const float*)d_in[0];
    const float* W1  = (const float*)d_in[1];
    const float* U1  = (const float*)d_in[2];
    const float* bi1 = (const float*)d_in[3];
    const float* br1 = (const float*)d_in[4];
    const float* W2  = (const float*)d_in[5];
    const float* U2  = (const float*)d_in[6];
    const float* bi2 = (const float*)d_in[7];
    const float* br2 = (const float*)d_in[8];
    const float* Wd  = (const float*)d_in[9];
    const float* bd  = (const float*)d_in[10];
    float* out = (float*)d_out;

    float *xT, *hseq, *h1, *h2; int* bars;
    cudaGetSymbolAddress((void**)&xT,   g_xT);
    cudaGetSymbolAddress((void**)&hseq, g_hseq);
    cudaGetSymbolAddress((void**)&h1,   g_h1);
    cudaGetSymbolAddress((void**)&h2,   g_h2);
    cudaGetSymbolAddress((void**)&bars, g_bar);

    cudaFuncSetAttribute(gru_persist, cudaFuncAttributeMaxDynamicSharedMemorySize,
                         (int)sizeof(Smem));

    init_kernel<<<(UU * BB + 255) / 256, 256>>>(h1, h2, bars);
    transpose_x<<<dim3(TT, 4, 4), dim3(32, 8)>>>(x, xT);
    gru_persist<<<NCTA, NTHR, sizeof(Smem)>>>(
        xT, W1, U1, bi1, br1, W2, U2, bi2, br2, hseq, h1, h2, bars);
    head_kernel<<<1, BB>>>(h2, Wd, bd, out);   // final h2 in buffer 0 after 512 steps
}

// round 4
// speedup vs baseline: 1.5916x; 1.5916x over previous
#include <cuda_runtime.h>
#include <cstdint>

typedef unsigned long long ull;

#define BB   128
#define TT   512
#define FF   128
#define UU   512
#define G3   1536
#define NCTA 128
#define NTHR 256
#define KC   32

#define UPC  8            // units per CTA
#define AREG 260          // floats per bg region in act buffer (KC*8 + 4 pad)
#define ABUF (8 * AREG)   // 2080 floats per act buffer

// SMEM float offsets
#define OFF_W1X 0          // 128*24  = 3072
#define OFF_U1  3072       // 512*24  = 12288
#define OFF_W2  15360      // 512*24  = 12288
#define OFF_U2  27648      // 512*24  = 12288
#define OFF_ACT 39936      // 2*2080  = 4160
#define OFF_RA  44096      // 3072 ull = 6144 floats
#define OFF_RB  50240      // 6144
#define SMEM_FLOATS 56384  // 225536 bytes

// ---------------- static device scratch ----------------
__device__ __align__(128) float g_xT[(size_t)TT * FF * BB];  // (T, F, B)
__device__ __align__(128) float g_h1[2 * UU * BB];
__device__ __align__(128) float g_h2[2 * UU * BB];
__device__ int g_bar[TT + 2];

// ---------------- helpers ----------------
__device__ __forceinline__ ull fma2(ull a, ull b, ull c) {
    ull d; asm("fma.rn.f32x2 %0, %1, %2, %3;" : "=l"(d) : "l"(a), "l"(b), "l"(c)); return d;
}
__device__ __forceinline__ ull add2(ull a, ull b) {
    ull d; asm("add.rn.f32x2 %0, %1, %2;" : "=l"(d) : "l"(a), "l"(b)); return d;
}
__device__ __forceinline__ ull pack2(float f) {
    ull d; asm("mov.b64 %0, {%1, %1};" : "=l"(d) : "f"(f)); return d;
}
__device__ __forceinline__ float2 asf2(ull v) {
    float2 f; asm("mov.b64 {%0, %1}, %2;" : "=f"(f.x), "=f"(f.y) : "l"(v)); return f;
}
__device__ __forceinline__ float sigm(float v) { return 1.0f / (1.0f + __expf(-v)); }

__device__ __forceinline__ void grid_barrier(int* bar) {
    __syncthreads();
    if (threadIdx.x == 0) {
        asm volatile("red.release.gpu.global.add.u32 [%0], 1;" :: "l"(bar) : "memory");
        int v;
        do {
            asm volatile("ld.acquire.gpu.global.u32 %0, [%1];" : "=r"(v) : "l"(bar) : "memory");
        } while (v < NCTA);
    }
    __syncthreads();
}

// global weight slab -> smem [k][u*3+g], cols g*512 + ug*8 + u
__device__ void load_w(float* dst, const float* src, int R, int ug, int tid) {
    for (int idx = tid; idx < R * 24; idx += NTHR) {
        int k = idx / 24, c = idx - k * 24;
        int u = c / 3, g = c - u * 3;
        dst[idx] = src[(size_t)k * G3 + g * UU + ug * 8 + u];
    }
}

// stream one KC x 64-batch chunk into bg-region layout
// chunk = KC*64 floats = 2048 floats = 512 float4 -> 2 per thread
__device__ __forceinline__ void cp_chunk(float* dstbuf, const float* src, int tid) {
    uint32_t d0 = (uint32_t)__cvta_generic_to_shared(dstbuf);
    #pragma unroll
    for (int i = 0; i < 2; i++) {
        int f = tid + NTHR * i;           // 0..511
        int k = f >> 4, seg = f & 15;     // k: 0..31, seg: 0..15
        int bgr = seg >> 1, half = seg & 1;
        uint32_t da = d0 + (uint32_t)((bgr * AREG + k * 8 + half * 4) * 4);
        const float* s = src + (size_t)k * BB + seg * 4;
        asm volatile("cp.async.cg.shared.global [%0], [%1], 16;" :: "r"(da), "l"(s) : "memory");
    }
    asm volatile("cp.async.commit_group;" ::: "memory");
}
__device__ __forceinline__ void cp_wait() {
    asm volatile("cp.async.wait_group 0;" ::: "memory");
}

// single-layer chunk: 12 FMA2 per k
__device__ __forceinline__ void cc1(const float* A, const float* w, int kg, int unit, int bg,
                                    ull* az, ull* ar, ull* ah) {
    #pragma unroll
    for (int i = 0; i < KC / 4; i++) {
        int k = 4 * i + kg;
        const float* ap = A + bg * AREG + k * 8;
        ulonglong2 p01 = *reinterpret_cast<const ulonglong2*>(ap);
        ulonglong2 p23 = *reinterpret_cast<const ulonglong2*>(ap + 4);
        const float* wp = w + k * 24 + unit * 3;
        ull wz = pack2(wp[0]), wr = pack2(wp[1]), wh = pack2(wp[2]);
        az[0] = fma2(p01.x, wz, az[0]); az[1] = fma2(p01.y, wz, az[1]);
        az[2] = fma2(p23.x, wz, az[2]); az[3] = fma2(p23.y, wz, az[3]);
        ar[0] = fma2(p01.x, wr, ar[0]); ar[1] = fma2(p01.y, wr, ar[1]);
        ar[2] = fma2(p23.x, wr, ar[2]); ar[3] = fma2(p23.y, wr, ar[3]);
        ah[0] = fma2(p01.x, wh, ah[0]); ah[1] = fma2(p01.y, wh, ah[1]);
        ah[2] = fma2(p23.x, wh, ah[2]); ah[3] = fma2(p23.y, wh, ah[3]);
    }
}

// dual-layer chunk over h1 rows: acts read once, 24 FMA2 per k
__device__ __forceinline__ void cc2(const float* A, const float* wa, const float* wb,
                                    int kg, int unit, int bg,
                                    ull* az1, ull* ar1, ull* ah1,
                                    ull* az2, ull* ar2, ull* ah2) {
    #pragma unroll
    for (int i = 0; i < KC / 4; i++) {
        int k = 4 * i + kg;
        const float* ap = A + bg * AREG + k * 8;
        ulonglong2 p01 = *reinterpret_cast<const ulonglong2*>(ap);
        ulonglong2 p23 = *reinterpret_cast<const ulonglong2*>(ap + 4);
        const float* wpa = wa + k * 24 + unit * 3;
        const float* wpb = wb + k * 24 + unit * 3;
        ull za = pack2(wpa[0]), ra = pack2(wpa[1]), ha = pack2(wpa[2]);
        ull zb = pack2(wpb[0]), rb = pack2(wpb[1]), hb = pack2(wpb[2]);
        az1[0] = fma2(p01.x, za, az1[0]); az1[1] = fma2(p01.y, za, az1[1]);
        az1[2] = fma2(p23.x, za, az1[2]); az1[3] = fma2(p23.y, za, az1[3]);
        ar1[0] = fma2(p01.x, ra, ar1[0]); ar1[1] = fma2(p01.y, ra, ar1[1]);
        ar1[2] = fma2(p23.x, ra, ar1[2]); ar1[3] = fma2(p23.y, ra, ar1[3]);
        ah1[0] = fma2(p01.x, ha, ah1[0]); ah1[1] = fma2(p01.y, ha, ah1[1]);
        ah1[2] = fma2(p23.x, ha, ah1[2]); ah1[3] = fma2(p23.y, ha, ah1[3]);
        az2[0] = fma2(p01.x, zb, az2[0]); az2[1] = fma2(p01.y, zb, az2[1]);
        az2[2] = fma2(p23.x, zb, az2[2]); az2[3] = fma2(p23.y, zb, az2[3]);
        ar2[0] = fma2(p01.x, rb, ar2[0]); ar2[1] = fma2(p01.y, rb, ar2[1]);
        ar2[2] = fma2(p23.x, rb, ar2[2]); ar2[3] = fma2(p23.y, rb, ar2[3]);
        ah2[0] = fma2(p01.x, hb, ah2[0]); ah2[1] = fma2(p01.y, hb, ah2[1]);
        ah2[2] = fma2(p23.x, hb, ah2[2]); ah2[3] = fma2(p23.y, hb, ah2[3]);
    }
}

__device__ __forceinline__ void finalize(const float* hprev, float* hnext,
                                         int j, int bbase,
                                         ull* z, ull* r, ull* hx, ull* hr,
                                         float bZ, float bR, float bHx, float bHr) {
    const float* hp = hprev + (size_t)j * BB + bbase;
    float4 h0 = __ldcg((const float4*)hp);
    float4 h1 = __ldcg((const float4*)(hp + 4));
    float hpv[8] = {h0.x, h0.y, h0.z, h0.w, h1.x, h1.y, h1.z, h1.w};
    float hn[8];
    #pragma unroll
    for (int p = 0; p < 4; p++) {
        float2 zz = asf2(z[p]), rr = asf2(r[p]), xx = asf2(hx[p]), hh = asf2(hr[p]);
        float zv = sigm(zz.x + bZ);
        float rv = sigm(rr.x + bR);
        float cand = fmaxf(xx.x + bHx + rv * (hh.x + bHr), 0.0f);
        hn[2 * p] = zv * hpv[2 * p] + (1.0f - zv) * cand;
        zv = sigm(zz.y + bZ);
        rv = sigm(rr.y + bR);
        cand = fmaxf(xx.y + bHx + rv * (hh.y + bHr), 0.0f);
        hn[2 * p + 1] = zv * hpv[2 * p + 1] + (1.0f - zv) * cand;
    }
    float* ho = hnext + (size_t)j * BB + bbase;
    *reinterpret_cast<float4*>(ho)     = make_float4(hn[0], hn[1], hn[2], hn[3]);
    *reinterpret_cast<float4*>(ho + 4) = make_float4(hn[4], hn[5], hn[6], hn[7]);
}

// ---------------------------------------------------------------------------
__global__ void __launch_bounds__(NTHR, 1) gru_persist(
    const float* __restrict__ xT,
    const float* __restrict__ W1, const float* __restrict__ U1,
    const float* __restrict__ bi1, const float* __restrict__ br1,
    const float* __restrict__ W2, const float* __restrict__ U2,
    const float* __restrict__ bi2, const float* __restrict__ br2,
    float* h1buf, float* h2buf, int* bars)
{
    extern __shared__ float smf[];
    float* sw1x = smf + OFF_W1X;
    float* su1  = smf + OFF_U1;
    float* sw2  = smf + OFF_W2;
    float* su2  = smf + OFF_U2;
    float* sact = smf + OFF_ACT;
    ull*   redA = (ull*)(smf + OFF_RA);
    ull*   redB = (ull*)(smf + OFF_RB);

    const int tid  = threadIdx.x;
    const int cta  = blockIdx.x;
    const int ug   = cta >> 1, bh = cta & 1;
    const int bg   = tid & 7;
    const int unit = (tid >> 3) & 7;
    const int kg   = tid >> 6;
    const int slot = unit * 8 + bg;
    const int j    = ug * 8 + unit;
    const int bbase = bh * 64 + bg * 8;

    load_w(sw1x, W1, FF, ug, tid);
    load_w(su1,  U1, UU, ug, tid);
    load_w(sw2,  W2, UU, ug, tid);
    load_w(su2,  U2, UU, ug, tid);

    const float b1Z = bi1[j] + br1[j];
    const float b1R = bi1[UU + j] + br1[UU + j];
    const float b1Hx = bi1[2 * UU + j];
    const float b1Hr = br1[2 * UU + j];
    const float b2Z = bi2[j] + br2[j];
    const float b2R = bi2[UU + j] + br2[UU + j];
    const float b2Hx = bi2[2 * UU + j];
    const float b2Hr = br2[2 * UU + j];
    __syncthreads();

    bool pre = false;
    #pragma unroll 1
    for (int t = 0; t <= TT; t++) {
        const bool doL1 = (t < TT), doL2 = (t > 0);
        const float* xs    = xT    + (size_t)t * FF * BB;
        const float* h1rec = h1buf + (size_t)(t & 1) * (UU * BB);
        float*       h1nx  = h1buf + (size_t)((t + 1) & 1) * (UU * BB);
        const float* h2rec = h2buf + (size_t)((t + 1) & 1) * (UU * BB);  // H2[t-1]
        float*       h2nx  = h2buf + (size_t)(t & 1) * (UU * BB);        // H2[t]
        const int xch = doL1 ? FF / KC : 0;          // 4 (0 at tail)
        const int h1c = UU / KC;                     // 16
        const int h2c = doL2 ? UU / KC : 0;          // 16 (0 at t=0)
        const int nch = xch + h1c + h2c;

        ull z1[4] = {0,0,0,0}, r1[4] = {0,0,0,0}, hx1[4] = {0,0,0,0}, hr1[4] = {0,0,0,0};
        ull z2[4] = {0,0,0,0}, r2[4] = {0,0,0,0}, hx2[4] = {0,0,0,0}, hr2[4] = {0,0,0,0};

        // chunk 0 issue (only when not prefetched): x chunk at t<TT, h1 chunk at tail
        if (!pre) {
            const float* s0 = (xch > 0) ? (xs + bh * 64) : (h1rec + bh * 64);
            cp_chunk(sact, s0, tid);
        }

        #pragma unroll 1
        for (int ch = 0; ch < nch; ch++) {
            cp_wait();
            __syncthreads();
            if (ch + 1 < nch) {
                const float* s;
                int c = ch + 1;
                if (c < xch)                 s = xs    + (size_t)c * KC * BB + bh * 64;
                else if (c < xch + h1c)      s = h1rec + (size_t)(c - xch) * KC * BB + bh * 64;
                else                         s = h2rec + (size_t)(c - xch - h1c) * KC * BB + bh * 64;
                cp_chunk(sact + (c & 1) * ABUF, s, tid);
            }
            const float* A = sact + (ch & 1) * ABUF;
            if (ch < xch) {
                cc1(A, sw1x + ch * KC * 24, kg, unit, bg, z1, r1, hx1);
            } else if (ch < xch + h1c) {
                int r0 = (ch - xch) * KC * 24;
                if (doL1 && doL2) cc2(A, su1 + r0, sw2 + r0, kg, unit, bg, z1, r1, hr1, z2, r2, hx2);
                else if (doL1)    cc1(A, su1 + r0, kg, unit, bg, z1, r1, hr1);
                else              cc1(A, sw2 + r0, kg, unit, bg, z2, r2, hx2);
            } else {
                int r0 = (ch - xch - h1c) * KC * 24;
                cc1(A, su2 + r0, kg, unit, bg, z2, r2, hr2);
            }
        }

        // store k-split partials (layer1: kg 1..3 -> redA; layer2: kg 0,2,3 -> redB)
        if (doL1 && kg != 0) {
            ull* base = redA + (size_t)(kg - 1) * 16 * 64 + slot;
            #pragma unroll
            for (int p = 0; p < 4; p++) {
                base[p * 64]        = z1[p];
                base[(4 + p) * 64]  = r1[p];
                base[(8 + p) * 64]  = hx1[p];
                base[(12 + p) * 64] = hr1[p];
            }
        }
        if (doL2 && kg != 1) {
            int s = (kg == 0) ? 0 : kg - 1;
            ull* base = redB + (size_t)s * 16 * 64 + slot;
            #pragma unroll
            for (int p = 0; p < 4; p++) {
                base[p * 64]        = z2[p];
                base[(4 + p) * 64]  = r2[p];
                base[(8 + p) * 64]  = hx2[p];
                base[(12 + p) * 64] = hr2[p];
            }
        }
        __syncthreads();

        // prefetch next superstep's x chunk0 (dependency-free) before barrier
        pre = (t + 1 < TT);
        if (pre)
            cp_chunk(sact, xT + (size_t)(t + 1) * FF * BB + bh * 64, tid);

        if (doL1 && kg == 0) {
            #pragma unroll
            for (int s = 0; s < 3; s++) {
                ull* base = redA + (size_t)s * 16 * 64 + slot;
                #pragma unroll
                for (int p = 0; p < 4; p++) {
                    z1[p]  = add2(z1[p],  base[p * 64]);
                    r1[p]  = add2(r1[p],  base[(4 + p) * 64]);
                    hx1[p] = add2(hx1[p], base[(8 + p) * 64]);
                    hr1[p] = add2(hr1[p], base[(12 + p) * 64]);
                }
            }
            finalize(h1rec, h1nx, j, bbase, z1, r1, hx1, hr1, b1Z, b1R, b1Hx, b1Hr);
        }
        if (doL2 && kg == 1) {
            #pragma unroll
            for (int s = 0; s < 3; s++) {
                ull* base = redB + (size_t)s * 16 * 64 + slot;
                #pragma unroll
                for (int p = 0; p < 4; p++) {
                    z2[p]  = add2(z2[p],  base[p * 64]);
                    r2[p]  = add2(r2[p],  base[(4 + p) * 64]);
                    hx2[p] = add2(hx2[p], base[(8 + p) * 64]);
                    hr2[p] = add2(hr2[p], base[(12 + p) * 64]);
                }
            }
            finalize(h2rec, h2nx, j, bbase, z2, r2, hx2, hr2, b2Z, b2R, b2Hx, b2Hr);
        }

        grid_barrier(&bars[t]);
    }
}

// ---------------------------------------------------------------------------
__global__ void init_kernel(float* h1, float* h2, int* bars)
{
    int i = blockIdx.x * blockDim.x + threadIdx.x;
    if (i < 2 * UU * BB) { h1[i] = 0.0f; h2[i] = 0.0f; }
    if (i < TT + 2) bars[i] = 0;
}

// x (B, T, F) -> xT (T, F, B)
__global__ void transpose_x(const float* __restrict__ x, float* __restrict__ xT)
{
    __shared__ float tile[32][33];
    const int t  = blockIdx.x;
    const int bb = blockIdx.y * 32;
    const int ib = blockIdx.z * 32;
    const int tx = threadIdx.x, ty = threadIdx.y;  // 32 x 8

    #pragma unroll
    for (int r = 0; r < 4; r++)
        tile[ty + 8 * r][tx] = x[(size_t)(bb + ty + 8 * r) * TT * FF + (size_t)t * FF + ib + tx];
    __syncthreads();
    #pragma unroll
    for (int r = 0; r < 4; r++)
        xT[(size_t)t * FF * BB + (size_t)(ib + ty + 8 * r) * BB + bb + tx] = tile[tx][ty + 8 * r];
}

__global__ void head_kernel(const float* __restrict__ h,   // (U, B) final h2
                            const float* __restrict__ Wd,
                            const float* __restrict__ bd,
                            float* __restrict__ out)
{
    __shared__ float part[4][BB];
    int b = threadIdx.x & 127, q = threadIdx.x >> 7;
    float acc = 0.0f;
    #pragma unroll 8
    for (int k = q * 128; k < (q + 1) * 128; k++)
        acc += h[(size_t)k * BB + b] * __ldg(&Wd[k]);
    part[q][b] = acc;
    __syncthreads();
    if (q == 0)
        out[b] = part[0][b] + part[1][b] + part[2][b] + part[3][b] + bd[0];
}

// ---------------------------------------------------------------------------
extern "C" void kernel_launch(void* const* d_in, const int* in_sizes, int n_in,
                              void* d_out, int out_size)
{
    const float* x   = (const float*)d_in[0];
    const float* W1  = (const float*)d_in[1];
    const float* U1  = (const float*)d_in[2];
    const float* bi1 = (const float*)d_in[3];
    const float* br1 = (const float*)d_in[4];
    const float* W2  = (const float*)d_in[5];
    const float* U2  = (const float*)d_in[6];
    const float* bi2 = (const float*)d_in[7];
    const float* br2 = (const float*)d_in[8];
    const float* Wd  = (const float*)d_in[9];
    const float* bd  = (const float*)d_in[10];
    float* out = (float*)d_out;

    float *xT, *h1, *h2; int* bars;
    cudaGetSymbolAddress((void**)&xT,   g_xT);
    cudaGetSymbolAddress((void**)&h1,   g_h1);
    cudaGetSymbolAddress((void**)&h2,   g_h2);
    cudaGetSymbolAddress((void**)&bars, g_bar);

    cudaFuncSetAttribute(gru_persist, cudaFuncAttributeMaxDynamicSharedMemorySize,
                         SMEM_FLOATS * 4);

    init_kernel<<<(2 * UU * BB + 255) / 256, 256>>>(h1, h2, bars);
    transpose_x<<<dim3(TT, 4, 4), dim3(32, 8)>>>(x, xT);
    gru_persist<<<NCTA, NTHR, SMEM_FLOATS * 4>>>(
        xT, W1, U1, bi1, br1, W2, U2, bi2, br2, h1, h2, bars);
    // after tail superstep, final h2 lives in buffer 0
    head_kernel<<<1, 512>>>(h2, Wd, bd, out);
}